// round 8
// baseline (speedup 1.0000x reference)
#include <cuda_runtime.h>
#include <cuda_fp16.h>
#include <cstdint>

// ============================================================================
// QATLinear: y[t,o] = scale[o] * sum_i x[t,i]*sign(w[o,i]) + b[o]
//
// R8: B travels as PACKED SIGN BITS (16x less L2 feed for B); bits for chunk
// c+1 are expanded bit->fp16 into a smem double-buffer DURING chunk c's MMAs
// (producer-side, off the MMA-feed path -- unlike R4's consumer-side expand).
// L2 feed drops 17.2GB -> 9.1GB, below the ~6300 B/cyc LTS cap that R7
// evidence suggests is binding. One barrier per chunk preserved.
// Config: BM=BN=128, BK=64, 8 warps (32x64 tile), A-stages=4, 2 CTAs/SM.
// ============================================================================

#define TOKENS 8192
#define DIN    4096
#define DOUT   16384

static constexpr int BM = 128;
static constexpr int BN = 128;
static constexpr int BK = 64;
static constexpr int STAGES = 4;
static constexpr int THREADS = 256;              // 8 warps: 4 (m) x 2 (n)
static constexpr int NCHUNK = DIN / BK;          // 64
static constexpr int KWORDS = DIN / 32;          // 128

static constexpr int A_STAGE_B = BM * BK * 2;    // 16384 B
static constexpr int BITS_B    = BN * 2 * 4;     // 1024 B (2 kwords x 128 n)
static constexpr int STAGE_B   = A_STAGE_B + BITS_B;      // 17408
static constexpr int BEXP_OFF  = STAGES * STAGE_B;        // 69632
static constexpr int BEXP_B    = BN * BK * 2;             // 16384
static constexpr int SMEM_TOTAL = BEXP_OFF + 2 * BEXP_B;  // 102400 per CTA

// ---- scratch (device globals: allocation-free rule) ----
__device__ __half    g_A [(size_t)TOKENS * DIN];          // 64 MB (x fp16)
__device__ uint32_t  g_Bb[(size_t)KWORDS * DOUT];         // 8 MB (sign bits)
// g_Bb[kw * DOUT + n] bit j = (w[n][kw*32+j] < 0)

// ============================ PTX helpers ===================================
__device__ __forceinline__ uint32_t smem_u32(const void* p) {
    uint32_t a;
    asm("{ .reg .u64 t; cvta.to.shared.u64 t, %1; cvt.u32.u64 %0, t; }"
        : "=r"(a) : "l"(p));
    return a;
}
__device__ __forceinline__ void cp_async16(uint32_t saddr, const void* gptr) {
    asm volatile("cp.async.cg.shared.global [%0], [%1], 16;"
                 :: "r"(saddr), "l"(gptr) : "memory");
}
__device__ __forceinline__ void cp_commit() {
    asm volatile("cp.async.commit_group;" ::: "memory");
}
template <int N>
__device__ __forceinline__ void cp_wait() {
    asm volatile("cp.async.wait_group %0;" :: "n"(N) : "memory");
}
__device__ __forceinline__ void ldmatrix_x4(uint32_t& r0, uint32_t& r1,
                                            uint32_t& r2, uint32_t& r3,
                                            uint32_t addr) {
    asm volatile("ldmatrix.sync.aligned.m8n8.x4.shared.b16 {%0,%1,%2,%3}, [%4];"
                 : "=r"(r0), "=r"(r1), "=r"(r2), "=r"(r3) : "r"(addr));
}
__device__ __forceinline__ uint32_t lds32(uint32_t addr) {
    uint32_t v;
    asm volatile("ld.shared.b32 %0, [%1];" : "=r"(v) : "r"(addr));
    return v;
}
#define STS128(addr, r0, r1, r2, r3) \
    asm volatile("st.shared.v4.b32 [%0], {%1, %2, %3, %4};" \
                 :: "r"(addr), "r"(r0), "r"(r1), "r"(r2), "r"(r3) : "memory")
__device__ __forceinline__ void mma_16816(float* c, const uint32_t* a,
                                          const uint32_t* b) {
    asm volatile(
        "mma.sync.aligned.m16n8k16.row.col.f32.f16.f16.f32 "
        "{%0,%1,%2,%3}, {%4,%5,%6,%7}, {%8,%9}, {%0,%1,%2,%3};"
        : "+f"(c[0]), "+f"(c[1]), "+f"(c[2]), "+f"(c[3])
        : "r"(a[0]), "r"(a[1]), "r"(a[2]), "r"(a[3]), "r"(b[0]), "r"(b[1]));
}
// tile rows: 64 fp16 = 128 B = 8 x 16B chunks; chunk' = chunk ^ (row&7)
__device__ __forceinline__ uint32_t sw_off(int row, int chunk) {
    return (uint32_t)((row << 7) + ((chunk ^ (row & 7)) << 4));
}

// ============================ prep kernels ==================================
__global__ void prep_a_kernel(const float* __restrict__ x) {
    size_t i = (size_t)blockIdx.x * blockDim.x + threadIdx.x;
    const size_t n4 = (size_t)TOKENS * DIN / 4;
    if (i >= n4) return;
    float4 v = __ldg((const float4*)x + i);
    uint32_t h0 = __half_as_ushort(__float2half_rn(v.x))
                | ((uint32_t)__half_as_ushort(__float2half_rn(v.y)) << 16);
    uint32_t h1 = __half_as_ushort(__float2half_rn(v.z))
                | ((uint32_t)__half_as_ushort(__float2half_rn(v.w)) << 16);
    uint2 p; p.x = h0; p.y = h1;
    ((uint2*)g_A)[i] = p;
}
// ballot-pack sign bits; bit=1 <=> w<0 (0,-0 -> +1 like reference)
__global__ void prep_b_kernel(const float* __restrict__ w) {
    size_t g = (size_t)blockIdx.x * blockDim.x + threadIdx.x;  // over DOUT*DIN
    float v = __ldg(w + g);
    uint32_t word = __ballot_sync(0xFFFFFFFFu, v < 0.0f);
    if ((threadIdx.x & 31) == 0) {
        size_t n  = g / DIN;
        size_t kw = (g % DIN) >> 5;
        g_Bb[kw * DOUT + n] = word;
    }
}

// ============================ GEMM kernel ===================================
__global__ void __launch_bounds__(THREADS, 2)
qat_gemm_kernel(const float* __restrict__ scale, const float* __restrict__ bias,
                float* __restrict__ out) {
    extern __shared__ char smem[];
    const uint32_t sbase = smem_u32(smem);
    const int tid  = threadIdx.x;
    const int wid  = tid >> 5;
    const int lane = tid & 31;

    // grouped tile swizzle (GROUP_M = 8): 64 m-tiles x 128 n-tiles
    const int pid   = blockIdx.x;                 // 0 .. 8191
    const int group = pid >> 10;
    const int inb   = pid & 1023;
    const int pid_m = (group << 3) + (inb & 7);
    const int pid_n = inb >> 3;
    const int m0 = pid_m * BM;
    const int n0 = pid_n * BN;

    // phase stagger: wave partners anti-align k-loops (R7 win, kept)
    const int coff = ((pid / 148) & 1) ? (NCHUNK / 2) : 0;

    // warp tile: 32 (m) x 64 (n); warps: 4 (m) x 2 (n)
    const int warp_m = wid & 3;
    const int warp_n = wid >> 2;
    const int wm0 = warp_m * 32;
    const int wn0 = warp_n * 64;

    // ---- A global load indices (16B per cp.async; rows are 8x16B chunks) ---
    const int g_row = tid >> 3;               // 0..31
    const int g_chk = tid & 7;
    const __half* gA0 = g_A + (size_t)(m0 + g_row) * DIN + g_chk * 8;
    const __half* gA1 = gA0 + (size_t)32 * DIN;
    const __half* gA2 = gA0 + (size_t)64 * DIN;
    const __half* gA3 = gA0 + (size_t)96 * DIN;
    const uint32_t sO0 = sw_off(g_row,      g_chk);
    const uint32_t sO1 = sw_off(g_row + 32, g_chk);
    const uint32_t sO2 = sw_off(g_row + 64, g_chk);
    const uint32_t sO3 = sw_off(g_row + 96, g_chk);

    // cc = pipeline position (slot = cc % STAGES); gmem chunk = rotated
    auto issue_stage = [&](int cc) {
        const int s = cc % STAGES;
        const int c = (cc + coff) & (NCHUNK - 1);
        const uint32_t stA = sbase + s * STAGE_B;
        const size_t kofs = (size_t)c * BK;
        cp_async16(stA + sO0, gA0 + kofs);
        cp_async16(stA + sO1, gA1 + kofs);
        cp_async16(stA + sO2, gA2 + kofs);
        cp_async16(stA + sO3, gA3 + kofs);
        if (tid < 64) {
            // bits: 2 kwords x 128 n = 1KB; kw = tid>>5, 4 n-words per thread
            const int kw = tid >> 5, nq = tid & 31;
            cp_async16(stA + A_STAGE_B + (kw << 9) + nq * 16,
                       g_Bb + (size_t)(2 * c + kw) * DOUT + n0 + nq * 4);
        }
    };

    // expand bits in stage slot -> bExp buffer (fp16 +-1 tile, swizzled)
    auto expand = [&](int cc) {
        const uint32_t stBits = sbase + (cc % STAGES) * STAGE_B + A_STAGE_B;
        const uint32_t bexp   = sbase + BEXP_OFF + (cc & 1) * BEXP_B;
        const int r  = tid & 127;
        const int kw = tid >> 7;
        const uint32_t W = lds32(stBits + (kw << 9) + (r << 2));
        const uint32_t rowbase = bexp + (r << 7);
        const int rx = r & 7;
#pragma unroll
        for (int q = 0; q < 4; ++q) {
            const uint32_t u = W >> (q * 8);
            uint32_t w0 = 0x3C003C00u | ((u & 1u) << 15) | ((u & 2u) << 30);
            uint32_t w1 = 0x3C003C00u | (((u >> 2) & 1u) << 15) | (((u >> 2) & 2u) << 30);
            uint32_t w2 = 0x3C003C00u | (((u >> 4) & 1u) << 15) | (((u >> 4) & 2u) << 30);
            uint32_t w3 = 0x3C003C00u | (((u >> 6) & 1u) << 15) | (((u >> 6) & 2u) << 30);
            const int chunkIdx = 4 * kw + q;
            STS128(rowbase + (uint32_t)((chunkIdx ^ rx) << 4), w0, w1, w2, w3);
        }
    };

    // ---- prologue: fill STAGES-1 stages, pre-expand chunk 0 ----
#pragma unroll
    for (int cc = 0; cc < STAGES - 1; ++cc) { issue_stage(cc); cp_commit(); }
    cp_wait<STAGES - 2>();     // group 0 complete -> bits(0) in smem
    __syncthreads();
    expand(0);

    // ---- accumulators: 2 m-frags x 8 n-frags x 4 ----
    float acc[2][8][4];
#pragma unroll
    for (int i = 0; i < 2; ++i)
#pragma unroll
        for (int j = 0; j < 8; ++j)
#pragma unroll
            for (int q = 0; q < 4; ++q) acc[i][j][q] = 0.0f;

    const int lquad = lane >> 3;
    const int lrow  = lane & 7;

#pragma unroll 1
    for (int cc = 0; cc < NCHUNK; ++cc) {
        // need A(cc) AND bits(cc+1): allow only 1 group in flight
        cp_wait<1>();
        __syncthreads();   // all warps done reading slot cc-1 & bExp[cc-1]

        if (cc + STAGES - 1 < NCHUNK) { issue_stage(cc + STAGES - 1); cp_commit(); }
        if (cc + 1 < NCHUNK) expand(cc + 1);   // off-path: overlaps MMAs below

        const uint32_t stA = sbase + (cc % STAGES) * STAGE_B;
        const uint32_t stB = sbase + BEXP_OFF + (cc & 1) * BEXP_B;

#pragma unroll
        for (int kh = 0; kh < 4; ++kh) {      // four k16 halves of BK=64
            const int kchunk = kh * 2;

            uint32_t afr[2][4];
#pragma unroll
            for (int mi = 0; mi < 2; ++mi) {
                int row = wm0 + mi * 16 + lrow + ((lquad & 1) << 3);
                int chk = kchunk + (lquad >> 1);
                ldmatrix_x4(afr[mi][0], afr[mi][1], afr[mi][2], afr[mi][3],
                            stA + sw_off(row, chk));
            }
            uint32_t bfr[8][2];
#pragma unroll
            for (int jp = 0; jp < 4; ++jp) {
                int row = wn0 + jp * 16 + lrow + ((lquad >> 1) << 3);
                int chk = kchunk + (lquad & 1);
                uint32_t r0, r1, r2, r3;
                ldmatrix_x4(r0, r1, r2, r3, stB + sw_off(row, chk));
                bfr[jp * 2 + 0][0] = r0; bfr[jp * 2 + 0][1] = r1;
                bfr[jp * 2 + 1][0] = r2; bfr[jp * 2 + 1][1] = r3;
            }
#pragma unroll
            for (int mi = 0; mi < 2; ++mi)
#pragma unroll
                for (int j = 0; j < 8; ++j)
                    mma_16816(acc[mi][j], afr[mi], bfr[j]);
        }
    }

    // ---- epilogue: fused scale/bias, float2 stores ----
    const int tq = lane >> 2;
    const int tr = lane & 3;
#pragma unroll
    for (int j = 0; j < 8; ++j) {
        const int n = n0 + wn0 + j * 8 + 2 * tr;
        const float2 sc = *(const float2*)(scale + n);
        const float2 bb = *(const float2*)(bias + n);
#pragma unroll
        for (int mi = 0; mi < 2; ++mi) {
            const int mrow = m0 + wm0 + mi * 16 + tq;
            float2 v0, v1;
            v0.x = fmaf(sc.x, acc[mi][j][0], bb.x);
            v0.y = fmaf(sc.y, acc[mi][j][1], bb.y);
            v1.x = fmaf(sc.x, acc[mi][j][2], bb.x);
            v1.y = fmaf(sc.y, acc[mi][j][3], bb.y);
            *(float2*)(out + (size_t)mrow * DOUT + n) = v0;
            *(float2*)(out + (size_t)(mrow + 8) * DOUT + n) = v1;
        }
    }
}

// ============================ launch ========================================
extern "C" void kernel_launch(void* const* d_in, const int* in_sizes, int n_in,
                              void* d_out, int out_size) {
    (void)in_sizes; (void)n_in; (void)out_size;
    const float* x     = (const float*)d_in[0];
    const float* w     = (const float*)d_in[1];
    const float* scale = (const float*)d_in[2];
    const float* b     = (const float*)d_in[3];
    float* out = (float*)d_out;

    {
        size_t n4 = (size_t)TOKENS * DIN / 4;
        prep_a_kernel<<<(unsigned)((n4 + 255) / 256), 256>>>(x);
    }
    {
        size_t nt = (size_t)DOUT * DIN;
        prep_b_kernel<<<(unsigned)((nt + 255) / 256), 256>>>(w);
    }

    cudaFuncSetAttribute(qat_gemm_kernel,
                         cudaFuncAttributeMaxDynamicSharedMemorySize,
                         SMEM_TOTAL);
    const int grid = (TOKENS / BM) * (DOUT / BN);   // 8192
    qat_gemm_kernel<<<grid, THREADS, SMEM_TOTAL>>>(scale, b, out);
}